// round 1
// baseline (speedup 1.0000x reference)
#include <cuda_runtime.h>
#include <math.h>

#define SEQ 2048
#define HIDDEN 4096
#define NQH 32
#define NKVH 8
#define HD 128
#define QDIM (NQH*HD)      /* 4096 */
#define KVDIM (NKVH*HD)    /* 1024 */
#define WINDOW 1024
#define SCALING 0.08838834764831845f  /* 128^-0.5 */

/* scratch (allocation-free rule: __device__ globals) */
__device__ float g_q[SEQ*QDIM];
__device__ float g_k[SEQ*KVDIM];
__device__ float g_v[SEQ*KVDIM];
__device__ float g_attn[SEQ*QDIM];

/* ------------------------- SGEMM 128x128x8, 256 thr, 8x8 micro ------------------------- */
#define BM 128
#define BN 128
#define BK 8
#define TM 8
#define TN 8

__global__ __launch_bounds__(256) void sgemm_kernel(
    const float* __restrict__ A, const float* __restrict__ B, float* __restrict__ C,
    int M, int N, int K)
{
    __shared__ float As[BK][BM];
    __shared__ float Bs[BK][BN];

    int tid = threadIdx.x;
    int tx = tid % (BN / TN);   /* 0..15 */
    int ty = tid / (BN / TN);   /* 0..15 */

    const float* Ab = A + (size_t)blockIdx.y * BM * K;
    const float* Bb = B + (size_t)blockIdx.x * BN;

    float acc[TM][TN];
    #pragma unroll
    for (int i = 0; i < TM; i++)
        #pragma unroll
        for (int j = 0; j < TN; j++) acc[i][j] = 0.f;

    int arow = tid >> 1;          /* 0..127 */
    int acol = (tid & 1) * 4;     /* 0 or 4 */
    int brow = tid >> 5;          /* 0..7   */
    int bcol = (tid & 31) * 4;    /* 0..124 */

    for (int k0 = 0; k0 < K; k0 += BK) {
        float4 av = *(const float4*)(Ab + (size_t)arow * K + k0 + acol);
        As[acol + 0][arow] = av.x;
        As[acol + 1][arow] = av.y;
        As[acol + 2][arow] = av.z;
        As[acol + 3][arow] = av.w;
        float4 bv = *(const float4*)(Bb + (size_t)(k0 + brow) * N + bcol);
        *(float4*)&Bs[brow][bcol] = bv;
        __syncthreads();

        #pragma unroll
        for (int kk = 0; kk < BK; kk++) {
            float a[TM], b[TN];
            *(float4*)&a[0] = *(const float4*)&As[kk][ty * TM];
            *(float4*)&a[4] = *(const float4*)&As[kk][ty * TM + 4];
            *(float4*)&b[0] = *(const float4*)&Bs[kk][tx * TN];
            *(float4*)&b[4] = *(const float4*)&Bs[kk][tx * TN + 4];
            #pragma unroll
            for (int i = 0; i < TM; i++)
                #pragma unroll
                for (int j = 0; j < TN; j++) acc[i][j] += a[i] * b[j];
        }
        __syncthreads();
    }

    float* Cb = C + (size_t)(blockIdx.y * BM + ty * TM) * N + blockIdx.x * BN + tx * TN;
    #pragma unroll
    for (int i = 0; i < TM; i++) {
        #pragma unroll
        for (int j = 0; j < TN; j += 4) {
            float4 v;
            v.x = acc[i][j + 0]; v.y = acc[i][j + 1];
            v.z = acc[i][j + 2]; v.w = acc[i][j + 3];
            *(float4*)(Cb + (size_t)i * N + j) = v;
        }
    }
}

/* ------------------------- RoPE (NeoX) ------------------------- */
__global__ void rope_kernel(float* x, const int* __restrict__ positions, int nheads)
{
    int idx = blockIdx.x * blockDim.x + threadIdx.x;
    int total = SEQ * nheads * (HD / 2);
    if (idx >= total) return;
    int i = idx & 63;                   /* freq index 0..63 */
    int h = (idx >> 6) % nheads;
    int s = idx / (64 * nheads);
    /* inv_freq = theta^(-i/64); use precise path to match fp32 reference */
    float inv = powf(1000000.0f, -(float)i * (1.0f / 64.0f));
    float f = (float)positions[s] * inv;
    float c = cosf(f), sn = sinf(f);
    float* base = x + ((size_t)s * nheads + h) * HD;
    float x1 = base[i], x2 = base[i + 64];
    base[i]      = x1 * c - x2 * sn;
    base[i + 64] = x2 * c + x1 * sn;
}

/* ------------------------- Attention (flash-style, unnormalized-exp softmax) ----------- */
#define QT 128
#define KT 64

__global__ __launch_bounds__(QT, 1) void attn_kernel(const float* __restrict__ sink)
{
    extern __shared__ float sm[];
    float* qs = sm;                 /* [HD][QT] transposed: qs[d*QT + r] */
    float* ks = sm + QT * HD;       /* [KT][HD] */
    float* vs = ks + KT * HD;       /* [KT][HD] */

    int h  = blockIdx.y;
    int q0 = blockIdx.x * QT;
    int t  = threadIdx.x;           /* 0..127, one query per thread */
    int kvh = h >> 2;               /* 32 q heads -> 8 kv heads, groups=4 */

    /* cooperative coalesced load of Q tile (transposed into smem) */
    for (int idx = t; idx < QT * HD; idx += QT) {
        int r = idx / HD, d = idx % HD;
        qs[d * QT + r] = g_q[(size_t)(q0 + r) * QDIM + h * HD + d];
    }
    __syncthreads();

    int qi = q0 + t;
    float o[HD];
    #pragma unroll
    for (int d = 0; d < HD; d++) o[d] = 0.f;
    float l = __expf(sink[h]);      /* exp(sink - 0); logits are small -> no max shift needed */

    int jlo = q0 - (WINDOW - 1);
    if (jlo < 0) jlo = 0;
    int kt0 = (jlo / KT) * KT;

    for (int kt = kt0; kt < q0 + QT; kt += KT) {
        for (int idx = t; idx < KT * HD; idx += QT) {
            int r = idx / HD, d = idx % HD;
            size_t g = (size_t)(kt + r) * KVDIM + kvh * HD + d;
            ks[idx] = g_k[g];
            vs[idx] = g_v[g];
        }
        __syncthreads();

        #pragma unroll 1
        for (int j = 0; j < KT; j++) {
            int gj = kt + j;
            if (gj <= qi && (qi - gj) < WINDOW) {
                float s0 = 0.f, s1 = 0.f, s2 = 0.f, s3 = 0.f;
                #pragma unroll
                for (int d = 0; d < HD; d += 4) {
                    s0 += qs[(d + 0) * QT + t] * ks[j * HD + d + 0];
                    s1 += qs[(d + 1) * QT + t] * ks[j * HD + d + 1];
                    s2 += qs[(d + 2) * QT + t] * ks[j * HD + d + 2];
                    s3 += qs[(d + 3) * QT + t] * ks[j * HD + d + 3];
                }
                float p = __expf(((s0 + s1) + (s2 + s3)) * SCALING);
                l += p;
                #pragma unroll
                for (int d = 0; d < HD; d += 4) {
                    float4 vv = *(const float4*)&vs[j * HD + d];
                    o[d + 0] += p * vv.x;
                    o[d + 1] += p * vv.y;
                    o[d + 2] += p * vv.z;
                    o[d + 3] += p * vv.w;
                }
            }
        }
        __syncthreads();
    }

    float inv = 1.0f / l;
    float* out = g_attn + (size_t)qi * QDIM + h * HD;
    #pragma unroll
    for (int d = 0; d < HD; d += 4) {
        float4 v;
        v.x = o[d + 0] * inv; v.y = o[d + 1] * inv;
        v.z = o[d + 2] * inv; v.w = o[d + 3] * inv;
        *(float4*)(out + d) = v;
    }
}

/* ------------------------- launch ------------------------- */
extern "C" void kernel_launch(void* const* d_in, const int* in_sizes, int n_in,
                              void* d_out, int out_size)
{
    const float* hs   = (const float*)d_in[0];
    const int*   pos  = (const int*)d_in[1];
    const float* wq   = (const float*)d_in[2];
    const float* wk   = (const float*)d_in[3];
    const float* wv   = (const float*)d_in[4];
    const float* wo   = (const float*)d_in[5];
    const float* sink = (const float*)d_in[6];
    float* out = (float*)d_out;

    float *q_ptr, *k_ptr, *v_ptr, *attn_ptr;
    cudaGetSymbolAddress((void**)&q_ptr, g_q);
    cudaGetSymbolAddress((void**)&k_ptr, g_k);
    cudaGetSymbolAddress((void**)&v_ptr, g_v);
    cudaGetSymbolAddress((void**)&attn_ptr, g_attn);

    /* QKV projections */
    sgemm_kernel<<<dim3(QDIM / BN, SEQ / BM), 256>>>(hs, wq, q_ptr, SEQ, QDIM, HIDDEN);
    sgemm_kernel<<<dim3(KVDIM / BN, SEQ / BM), 256>>>(hs, wk, k_ptr, SEQ, KVDIM, HIDDEN);
    sgemm_kernel<<<dim3(KVDIM / BN, SEQ / BM), 256>>>(hs, wv, v_ptr, SEQ, KVDIM, HIDDEN);

    /* RoPE on q and k */
    {
        int tq = SEQ * NQH * (HD / 2);
        rope_kernel<<<(tq + 255) / 256, 256>>>(q_ptr, pos, NQH);
        int tk = SEQ * NKVH * (HD / 2);
        rope_kernel<<<(tk + 255) / 256, 256>>>(k_ptr, pos, NKVH);
    }

    /* attention */
    {
        int smem = (QT * HD + 2 * KT * HD) * (int)sizeof(float);  /* 128 KB */
        cudaFuncSetAttribute(attn_kernel, cudaFuncAttributeMaxDynamicSharedMemorySize, smem);
        attn_kernel<<<dim3(SEQ / QT, NQH), QT, smem>>>(sink);
    }

    /* output projection */
    sgemm_kernel<<<dim3(HIDDEN / BN, SEQ / BM), 256>>>(attn_ptr, wo, out, SEQ, HIDDEN, QDIM);
}

// round 2
// speedup vs baseline: 1.7217x; 1.7217x over previous
#include <cuda_runtime.h>
#include <math.h>
#include <stdint.h>

#define SEQ 2048
#define HIDDEN 4096
#define NQH 32
#define NKVH 8
#define HD 128
#define QDIM (NQH*HD)      /* 4096 */
#define KVDIM (NKVH*HD)    /* 1024 */
#define WINDOW 1024
#define SCALING 0.08838834764831845f  /* 128^-0.5 */

/* scratch (allocation-free rule: __device__ globals) */
__device__ float g_q[SEQ*QDIM];
__device__ float g_k[SEQ*KVDIM];
__device__ float g_v[SEQ*KVDIM];
__device__ float g_attn[SEQ*QDIM];

/* ------------------------- TF32 tensor-core GEMM ------------------------- */
/* C[M,N] = A[M,K] @ B[K,N], row-major, all dims multiples of tile sizes.   */
/* 128x128x16 CTA tile, 8 warps, warp tile 64x32 via mma.m16n8k8.tf32.      */

#define GBM 128
#define GBN 128
#define GBK 16
#define GPAD 136   /* smem row stride in floats; 136 mod 32 = 8 -> conflict-free frags */

__device__ __forceinline__ uint32_t f2tf32(float f) {
    uint32_t u;
    asm("cvt.rna.tf32.f32 %0, %1;" : "=r"(u) : "f"(f));
    return u;
}

__global__ __launch_bounds__(256, 2) void tf32_gemm_kernel(
    const float* __restrict__ A, const float* __restrict__ B, float* __restrict__ C,
    int M, int N, int K)
{
    __shared__ uint32_t As[GBK][GPAD];   /* As[k][m] */
    __shared__ uint32_t Bs[GBK][GPAD];   /* Bs[k][n] */

    const int tid  = threadIdx.x;
    const int lane = tid & 31;
    const int wid  = tid >> 5;
    const int wm   = (wid & 1) * 64;     /* warp m offset within tile */
    const int wn   = (wid >> 1) * 32;    /* warp n offset within tile */
    const int t4   = lane & 3;
    const int g    = lane >> 2;

    const int bm0 = blockIdx.y * GBM;
    const int bn0 = blockIdx.x * GBN;

    float acc[4][4][4];
    #pragma unroll
    for (int i = 0; i < 4; i++)
        #pragma unroll
        for (int j = 0; j < 4; j++)
            #pragma unroll
            for (int r = 0; r < 4; r++) acc[i][j][r] = 0.f;

    /* global->shared load mapping */
    const int arow = tid >> 1;            /* 0..127 */
    const int ac4  = (tid & 1) * 2;       /* A f4-col base: 0 or 2 */
    const int brow = tid >> 4;            /* 0..15  */
    const int bc4  = (tid & 15) * 2;      /* B f4-col base: 0..30 */

    const float* Arow = A + (size_t)(bm0 + arow) * K;
    const float* Brow = B + (size_t)brow * N + bn0;

    for (int k0 = 0; k0 < K; k0 += GBK) {
        /* A tile: 128x16, convert to tf32, store transposed As[k][m] */
        #pragma unroll
        for (int s = 0; s < 2; s++) {
            float4 v = *(const float4*)(Arow + k0 + (ac4 + s) * 4);
            int kc = (ac4 + s) * 4;
            As[kc + 0][arow] = f2tf32(v.x);
            As[kc + 1][arow] = f2tf32(v.y);
            As[kc + 2][arow] = f2tf32(v.z);
            As[kc + 3][arow] = f2tf32(v.w);
        }
        /* B tile: 16x128, convert, store Bs[k][n] */
        #pragma unroll
        for (int s = 0; s < 2; s++) {
            float4 v = *(const float4*)(Brow + (size_t)k0 * N + (bc4 + s) * 4);
            uint32_t* p = &Bs[brow][(bc4 + s) * 4];
            p[0] = f2tf32(v.x); p[1] = f2tf32(v.y);
            p[2] = f2tf32(v.z); p[3] = f2tf32(v.w);
        }
        __syncthreads();

        #pragma unroll
        for (int ks = 0; ks < 2; ks++) {
            const int kk = ks * 8;
            uint32_t a[4][4], b[4][2];
            #pragma unroll
            for (int i = 0; i < 4; i++) {
                int mb = wm + i * 16;
                a[i][0] = As[kk + t4][mb + g];
                a[i][1] = As[kk + t4][mb + g + 8];
                a[i][2] = As[kk + t4 + 4][mb + g];
                a[i][3] = As[kk + t4 + 4][mb + g + 8];
            }
            #pragma unroll
            for (int j = 0; j < 4; j++) {
                int nb = wn + j * 8;
                b[j][0] = Bs[kk + t4][nb + g];
                b[j][1] = Bs[kk + t4 + 4][nb + g];
            }
            #pragma unroll
            for (int i = 0; i < 4; i++)
                #pragma unroll
                for (int j = 0; j < 4; j++) {
                    asm volatile(
                        "mma.sync.aligned.m16n8k8.row.col.f32.tf32.tf32.f32 "
                        "{%0,%1,%2,%3}, {%4,%5,%6,%7}, {%8,%9}, {%0,%1,%2,%3};"
                        : "+f"(acc[i][j][0]), "+f"(acc[i][j][1]),
                          "+f"(acc[i][j][2]), "+f"(acc[i][j][3])
                        : "r"(a[i][0]), "r"(a[i][1]), "r"(a[i][2]), "r"(a[i][3]),
                          "r"(b[j][0]), "r"(b[j][1]));
                }
        }
        __syncthreads();
    }

    /* epilogue */
    #pragma unroll
    for (int i = 0; i < 4; i++) {
        int row0 = bm0 + wm + i * 16 + g;
        #pragma unroll
        for (int j = 0; j < 4; j++) {
            int col = bn0 + wn + j * 8 + 2 * t4;
            float2 v01 = make_float2(acc[i][j][0], acc[i][j][1]);
            float2 v23 = make_float2(acc[i][j][2], acc[i][j][3]);
            *(float2*)(C + (size_t)row0 * N + col)       = v01;
            *(float2*)(C + (size_t)(row0 + 8) * N + col) = v23;
        }
    }
}

/* ------------------------- RoPE (NeoX) ------------------------- */
__global__ void rope_kernel(float* x, const int* __restrict__ positions, int nheads)
{
    int idx = blockIdx.x * blockDim.x + threadIdx.x;
    int total = SEQ * nheads * (HD / 2);
    if (idx >= total) return;
    int i = idx & 63;                   /* freq index 0..63 */
    int h = (idx >> 6) % nheads;
    int s = idx / (64 * nheads);
    float inv = powf(1000000.0f, -(float)i * (1.0f / 64.0f));
    float f = (float)positions[s] * inv;
    float c = cosf(f), sn = sinf(f);
    float* base = x + ((size_t)s * nheads + h) * HD;
    float x1 = base[i], x2 = base[i + 64];
    base[i]      = x1 * c - x2 * sn;
    base[i + 64] = x2 * c + x1 * sn;
}

/* ------------------------- Attention (flash-style, unnormalized-exp softmax) ----------- */
#define QT 128
#define KT 64

__global__ __launch_bounds__(QT, 1) void attn_kernel(const float* __restrict__ sink)
{
    extern __shared__ float sm[];
    float* qs = sm;                 /* [HD][QT] transposed: qs[d*QT + r] */
    float* ks = sm + QT * HD;       /* [KT][HD] */
    float* vs = ks + KT * HD;       /* [KT][HD] */

    int h  = blockIdx.y;
    int q0 = blockIdx.x * QT;
    int t  = threadIdx.x;           /* 0..127, one query per thread */
    int kvh = h >> 2;               /* 32 q heads -> 8 kv heads, groups=4 */

    for (int idx = t; idx < QT * HD; idx += QT) {
        int r = idx / HD, d = idx % HD;
        qs[d * QT + r] = g_q[(size_t)(q0 + r) * QDIM + h * HD + d];
    }
    __syncthreads();

    int qi = q0 + t;
    float o[HD];
    #pragma unroll
    for (int d = 0; d < HD; d++) o[d] = 0.f;
    float l = __expf(sink[h]);      /* logits small -> no max shift needed */

    int jlo = q0 - (WINDOW - 1);
    if (jlo < 0) jlo = 0;
    int kt0 = (jlo / KT) * KT;

    for (int kt = kt0; kt < q0 + QT; kt += KT) {
        for (int idx = t; idx < KT * HD; idx += QT) {
            int r = idx / HD, d = idx % HD;
            size_t gg = (size_t)(kt + r) * KVDIM + kvh * HD + d;
            ks[idx] = g_k[gg];
            vs[idx] = g_v[gg];
        }
        __syncthreads();

        #pragma unroll 1
        for (int j = 0; j < KT; j++) {
            int gj = kt + j;
            if (gj <= qi && (qi - gj) < WINDOW) {
                float s0 = 0.f, s1 = 0.f, s2 = 0.f, s3 = 0.f;
                #pragma unroll
                for (int d = 0; d < HD; d += 4) {
                    s0 += qs[(d + 0) * QT + t] * ks[j * HD + d + 0];
                    s1 += qs[(d + 1) * QT + t] * ks[j * HD + d + 1];
                    s2 += qs[(d + 2) * QT + t] * ks[j * HD + d + 2];
                    s3 += qs[(d + 3) * QT + t] * ks[j * HD + d + 3];
                }
                float p = __expf(((s0 + s1) + (s2 + s3)) * SCALING);
                l += p;
                #pragma unroll
                for (int d = 0; d < HD; d += 4) {
                    float4 vv = *(const float4*)&vs[j * HD + d];
                    o[d + 0] += p * vv.x;
                    o[d + 1] += p * vv.y;
                    o[d + 2] += p * vv.z;
                    o[d + 3] += p * vv.w;
                }
            }
        }
        __syncthreads();
    }

    float inv = 1.0f / l;
    float* out = g_attn + (size_t)qi * QDIM + h * HD;
    #pragma unroll
    for (int d = 0; d < HD; d += 4) {
        float4 v;
        v.x = o[d + 0] * inv; v.y = o[d + 1] * inv;
        v.z = o[d + 2] * inv; v.w = o[d + 3] * inv;
        *(float4*)(out + d) = v;
    }
}

/* ------------------------- launch ------------------------- */
extern "C" void kernel_launch(void* const* d_in, const int* in_sizes, int n_in,
                              void* d_out, int out_size)
{
    const float* hs   = (const float*)d_in[0];
    const int*   pos  = (const int*)d_in[1];
    const float* wq   = (const float*)d_in[2];
    const float* wk   = (const float*)d_in[3];
    const float* wv   = (const float*)d_in[4];
    const float* wo   = (const float*)d_in[5];
    const float* sink = (const float*)d_in[6];
    float* out = (float*)d_out;

    float *q_ptr, *k_ptr, *v_ptr, *attn_ptr;
    cudaGetSymbolAddress((void**)&q_ptr, g_q);
    cudaGetSymbolAddress((void**)&k_ptr, g_k);
    cudaGetSymbolAddress((void**)&v_ptr, g_v);
    cudaGetSymbolAddress((void**)&attn_ptr, g_attn);

    /* QKV projections (tensor cores, tf32) */
    tf32_gemm_kernel<<<dim3(QDIM / GBN, SEQ / GBM), 256>>>(hs, wq, q_ptr, SEQ, QDIM, HIDDEN);
    tf32_gemm_kernel<<<dim3(KVDIM / GBN, SEQ / GBM), 256>>>(hs, wk, k_ptr, SEQ, KVDIM, HIDDEN);
    tf32_gemm_kernel<<<dim3(KVDIM / GBN, SEQ / GBM), 256>>>(hs, wv, v_ptr, SEQ, KVDIM, HIDDEN);

    /* RoPE on q and k */
    {
        int tq = SEQ * NQH * (HD / 2);
        rope_kernel<<<(tq + 255) / 256, 256>>>(q_ptr, pos, NQH);
        int tk = SEQ * NKVH * (HD / 2);
        rope_kernel<<<(tk + 255) / 256, 256>>>(k_ptr, pos, NKVH);
    }

    /* attention */
    {
        int smem = (QT * HD + 2 * KT * HD) * (int)sizeof(float);  /* 128 KB */
        cudaFuncSetAttribute(attn_kernel, cudaFuncAttributeMaxDynamicSharedMemorySize, smem);
        attn_kernel<<<dim3(SEQ / QT, NQH), QT, smem>>>(sink);
    }

    /* output projection (tensor cores, tf32) */
    tf32_gemm_kernel<<<dim3(HIDDEN / GBN, SEQ / GBM), 256>>>(attn_ptr, wo, out, SEQ, HIDDEN, QDIM);
}

// round 3
// speedup vs baseline: 3.1996x; 1.8584x over previous
#include <cuda_runtime.h>
#include <cuda_bf16.h>
#include <math.h>
#include <stdint.h>

#define SEQ 2048
#define HIDDEN 4096
#define NQH 32
#define NKVH 8
#define HD 128
#define QDIM (NQH*HD)      /* 4096 */
#define KVDIM (NKVH*HD)    /* 1024 */
#define WINDOW 1024
#define SCALING 0.08838834764831845f  /* 128^-0.5 */

/* scratch (allocation-free rule: __device__ globals) */
__device__ float g_q[SEQ*QDIM];
__device__ float g_k[SEQ*KVDIM];
__device__ float g_v[SEQ*KVDIM];
__device__ float g_attn[SEQ*QDIM];

/* ------------------------- TF32 tensor-core GEMM (unchanged from R2) ---------------- */
#define GBM 128
#define GBN 128
#define GBK 16
#define GPAD 136

__device__ __forceinline__ uint32_t f2tf32(float f) {
    uint32_t u;
    asm("cvt.rna.tf32.f32 %0, %1;" : "=r"(u) : "f"(f));
    return u;
}

__global__ __launch_bounds__(256, 2) void tf32_gemm_kernel(
    const float* __restrict__ A, const float* __restrict__ B, float* __restrict__ C,
    int M, int N, int K)
{
    __shared__ uint32_t As[GBK][GPAD];   /* As[k][m] */
    __shared__ uint32_t Bs[GBK][GPAD];   /* Bs[k][n] */

    const int tid  = threadIdx.x;
    const int lane = tid & 31;
    const int wid  = tid >> 5;
    const int wm   = (wid & 1) * 64;
    const int wn   = (wid >> 1) * 32;
    const int t4   = lane & 3;
    const int g    = lane >> 2;

    const int bm0 = blockIdx.y * GBM;
    const int bn0 = blockIdx.x * GBN;

    float acc[4][4][4];
    #pragma unroll
    for (int i = 0; i < 4; i++)
        #pragma unroll
        for (int j = 0; j < 4; j++)
            #pragma unroll
            for (int r = 0; r < 4; r++) acc[i][j][r] = 0.f;

    const int arow = tid >> 1;
    const int ac4  = (tid & 1) * 2;
    const int brow = tid >> 4;
    const int bc4  = (tid & 15) * 2;

    const float* Arow = A + (size_t)(bm0 + arow) * K;
    const float* Brow = B + (size_t)brow * N + bn0;

    for (int k0 = 0; k0 < K; k0 += GBK) {
        #pragma unroll
        for (int s = 0; s < 2; s++) {
            float4 v = *(const float4*)(Arow + k0 + (ac4 + s) * 4);
            int kc = (ac4 + s) * 4;
            As[kc + 0][arow] = f2tf32(v.x);
            As[kc + 1][arow] = f2tf32(v.y);
            As[kc + 2][arow] = f2tf32(v.z);
            As[kc + 3][arow] = f2tf32(v.w);
        }
        #pragma unroll
        for (int s = 0; s < 2; s++) {
            float4 v = *(const float4*)(Brow + (size_t)k0 * N + (bc4 + s) * 4);
            uint32_t* p = &Bs[brow][(bc4 + s) * 4];
            p[0] = f2tf32(v.x); p[1] = f2tf32(v.y);
            p[2] = f2tf32(v.z); p[3] = f2tf32(v.w);
        }
        __syncthreads();

        #pragma unroll
        for (int ks = 0; ks < 2; ks++) {
            const int kk = ks * 8;
            uint32_t a[4][4], b[4][2];
            #pragma unroll
            for (int i = 0; i < 4; i++) {
                int mb = wm + i * 16;
                a[i][0] = As[kk + t4][mb + g];
                a[i][1] = As[kk + t4][mb + g + 8];
                a[i][2] = As[kk + t4 + 4][mb + g];
                a[i][3] = As[kk + t4 + 4][mb + g + 8];
            }
            #pragma unroll
            for (int j = 0; j < 4; j++) {
                int nb = wn + j * 8;
                b[j][0] = Bs[kk + t4][nb + g];
                b[j][1] = Bs[kk + t4 + 4][nb + g];
            }
            #pragma unroll
            for (int i = 0; i < 4; i++)
                #pragma unroll
                for (int j = 0; j < 4; j++) {
                    asm volatile(
                        "mma.sync.aligned.m16n8k8.row.col.f32.tf32.tf32.f32 "
                        "{%0,%1,%2,%3}, {%4,%5,%6,%7}, {%8,%9}, {%0,%1,%2,%3};"
                        : "+f"(acc[i][j][0]), "+f"(acc[i][j][1]),
                          "+f"(acc[i][j][2]), "+f"(acc[i][j][3])
                        : "r"(a[i][0]), "r"(a[i][1]), "r"(a[i][2]), "r"(a[i][3]),
                          "r"(b[j][0]), "r"(b[j][1]));
                }
        }
        __syncthreads();
    }

    #pragma unroll
    for (int i = 0; i < 4; i++) {
        int row0 = bm0 + wm + i * 16 + g;
        #pragma unroll
        for (int j = 0; j < 4; j++) {
            int col = bn0 + wn + j * 8 + 2 * t4;
            float2 v01 = make_float2(acc[i][j][0], acc[i][j][1]);
            float2 v23 = make_float2(acc[i][j][2], acc[i][j][3]);
            *(float2*)(C + (size_t)row0 * N + col)       = v01;
            *(float2*)(C + (size_t)(row0 + 8) * N + col) = v23;
        }
    }
}

/* ------------------------- RoPE (NeoX) ------------------------- */
__global__ void rope_kernel(float* x, const int* __restrict__ positions, int nheads)
{
    int idx = blockIdx.x * blockDim.x + threadIdx.x;
    int total = SEQ * nheads * (HD / 2);
    if (idx >= total) return;
    int i = idx & 63;
    int h = (idx >> 6) % nheads;
    int s = idx / (64 * nheads);
    float inv = powf(1000000.0f, -(float)i * (1.0f / 64.0f));
    float f = (float)positions[s] * inv;
    float c = cosf(f), sn = sinf(f);
    float* base = x + ((size_t)s * nheads + h) * HD;
    float x1 = base[i], x2 = base[i + 64];
    base[i]      = x1 * c - x2 * sn;
    base[i + 64] = x2 * c + x1 * sn;
}

/* ------------------------- Attention: bf16x3 tensor-core flash ------------------------- */
/* QT=128 rows/CTA, KT=64 kv/tile, 8 warps each owning 16 q rows.
   Q,K,V split hi/lo bf16 (x = bf16(x) + bf16(x - bf16(x))) -> 3 MMAs ~ fp32 precision.
   m16n8k16 fragment chaining: S C-frags -> P A-frags in registers.                       */

#define AQT 128
#define AKT 64
#define KPAD 68    /* word stride (uint32) for bf16 row tiles: 136 halves */
#define VPAD 136   /* word stride for j-pair-packed V rows               */

#define MMA_BF16(c, a0,a1,a2,a3, b0,b1)                                      \
    asm volatile("mma.sync.aligned.m16n8k16.row.col.f32.bf16.bf16.f32 "      \
        "{%0,%1,%2,%3}, {%4,%5,%6,%7}, {%8,%9}, {%0,%1,%2,%3};"              \
        : "+f"(c[0]), "+f"(c[1]), "+f"(c[2]), "+f"(c[3])                     \
        : "r"(a0), "r"(a1), "r"(a2), "r"(a3), "r"(b0), "r"(b1))

__device__ __forceinline__ void split2(float x, float y, uint32_t& hi, uint32_t& lo) {
    __nv_bfloat162 h = __float22bfloat162_rn(make_float2(x, y));
    float rx = x - __bfloat162float(h.x);
    float ry = y - __bfloat162float(h.y);
    __nv_bfloat162 l = __float22bfloat162_rn(make_float2(rx, ry));
    hi = *(uint32_t*)&h;
    lo = *(uint32_t*)&l;
}

__global__ __launch_bounds__(256, 1) void attn_mma_kernel(const float* __restrict__ sink)
{
    extern __shared__ uint32_t smw[];
    uint32_t* Qh = smw;                       /* [128][KPAD] */
    uint32_t* Ql = Qh + AQT * KPAD;
    uint32_t* Kh = Ql + AQT * KPAD;           /* [64][KPAD]  */
    uint32_t* Kl = Kh + AKT * KPAD;
    uint32_t* Vh = Kl + AKT * KPAD;           /* [32][VPAD] j-pair packed */
    uint32_t* Vl = Vh + (AKT/2) * VPAD;

    const int h   = blockIdx.y;
    const int q0  = blockIdx.x * AQT;
    const int kvh = h >> 2;
    const int tid = threadIdx.x;
    const int lane = tid & 31;
    const int wid  = tid >> 5;
    const int wrow = wid * 16;
    const int t4   = lane & 3;
    const int g    = lane >> 2;

    /* ---- load Q tile (128 x 128 floats), split to hi/lo bf16 ---- */
    {
        const float* Qg = g_q + (size_t)q0 * QDIM + h * HD;
        #pragma unroll
        for (int it = 0; it < 16; it++) {
            int slot = tid + it * 256;        /* 4096 float4 slots */
            int r = slot >> 5, d4 = slot & 31;
            float4 v = *(const float4*)(Qg + (size_t)r * QDIM + d4 * 4);
            uint32_t h01, l01, h23, l23;
            split2(v.x, v.y, h01, l01);
            split2(v.z, v.w, h23, l23);
            Qh[r * KPAD + d4 * 2]     = h01;
            Qh[r * KPAD + d4 * 2 + 1] = h23;
            Ql[r * KPAD + d4 * 2]     = l01;
            Ql[r * KPAD + d4 * 2 + 1] = l23;
        }
    }

    float o[16][4];
    #pragma unroll
    for (int i = 0; i < 16; i++)
        #pragma unroll
        for (int r = 0; r < 4; r++) o[i][r] = 0.f;
    float l0 = 0.f, l1 = 0.f;

    int jlo = q0 - (WINDOW - 1);
    if (jlo < 0) jlo = 0;
    int kt0 = (jlo / AKT) * AKT;

    const int qi0 = q0 + wrow + g;
    const int qi1 = qi0 + 8;

    for (int kt = kt0; kt < q0 + AQT; kt += AKT) {
        __syncthreads();   /* protect previous iteration's K/V reads */
        /* ---- load K tile (64 x 128) ---- */
        {
            const float* Kg = g_k + (size_t)kt * KVDIM + kvh * HD;
            #pragma unroll
            for (int it = 0; it < 8; it++) {
                int slot = tid + it * 256;    /* 2048 float4 slots */
                int r = slot >> 5, d4 = slot & 31;
                float4 v = *(const float4*)(Kg + (size_t)r * KVDIM + d4 * 4);
                uint32_t h01, l01, h23, l23;
                split2(v.x, v.y, h01, l01);
                split2(v.z, v.w, h23, l23);
                Kh[r * KPAD + d4 * 2]     = h01;
                Kh[r * KPAD + d4 * 2 + 1] = h23;
                Kl[r * KPAD + d4 * 2]     = l01;
                Kl[r * KPAD + d4 * 2 + 1] = l23;
            }
        }
        /* ---- load V tile (64 x 128), pack j-pairs ---- */
        {
            const float* Vg = g_v + (size_t)kt * KVDIM + kvh * HD;
            #pragma unroll
            for (int it = 0; it < 4; it++) {
                int slot = tid + it * 256;    /* 1024 slots: (rpair, d4) */
                int rp = slot >> 5, d4 = slot & 31;
                float4 v0 = *(const float4*)(Vg + (size_t)(2 * rp) * KVDIM + d4 * 4);
                float4 v1 = *(const float4*)(Vg + (size_t)(2 * rp + 1) * KVDIM + d4 * 4);
                const float* a = &v0.x;
                const float* b = &v1.x;
                #pragma unroll
                for (int jj = 0; jj < 4; jj++) {
                    uint32_t hi, lo;
                    split2(a[jj], b[jj], hi, lo);   /* low half = even j */
                    Vh[rp * VPAD + d4 * 4 + jj] = hi;
                    Vl[rp * VPAD + d4 * 4 + jj] = lo;
                }
            }
        }
        __syncthreads();

        /* ---- S = Q K^T over this tile (8 n-tiles x 8 k-steps, x3 split) ---- */
        float s[8][4];
        #pragma unroll
        for (int nt = 0; nt < 8; nt++)
            #pragma unroll
            for (int r = 0; r < 4; r++) s[nt][r] = 0.f;

        #pragma unroll
        for (int kk = 0; kk < 8; kk++) {
            const int kw = kk * 8;
            uint32_t ah0 = Qh[(wrow + g)     * KPAD + kw + t4];
            uint32_t ah1 = Qh[(wrow + g + 8) * KPAD + kw + t4];
            uint32_t ah2 = Qh[(wrow + g)     * KPAD + kw + t4 + 4];
            uint32_t ah3 = Qh[(wrow + g + 8) * KPAD + kw + t4 + 4];
            uint32_t al0 = Ql[(wrow + g)     * KPAD + kw + t4];
            uint32_t al1 = Ql[(wrow + g + 8) * KPAD + kw + t4];
            uint32_t al2 = Ql[(wrow + g)     * KPAD + kw + t4 + 4];
            uint32_t al3 = Ql[(wrow + g + 8) * KPAD + kw + t4 + 4];
            #pragma unroll
            for (int nt = 0; nt < 8; nt++) {
                const int krow = nt * 8 + g;
                uint32_t bh0 = Kh[krow * KPAD + kw + t4];
                uint32_t bh1 = Kh[krow * KPAD + kw + t4 + 4];
                uint32_t bl0 = Kl[krow * KPAD + kw + t4];
                uint32_t bl1 = Kl[krow * KPAD + kw + t4 + 4];
                MMA_BF16(s[nt], ah0, ah1, ah2, ah3, bh0, bh1);
                MMA_BF16(s[nt], ah0, ah1, ah2, ah3, bl0, bl1);
                MMA_BF16(s[nt], al0, al1, al2, al3, bh0, bh1);
            }
        }

        /* ---- mask + exp (unnormalized, sink handled at end) ---- */
        #pragma unroll
        for (int nt = 0; nt < 8; nt++) {
            int c0 = kt + nt * 8 + 2 * t4;
            int c1 = c0 + 1;
            float p0 = (c0 <= qi0 && qi0 - c0 < WINDOW) ? __expf(s[nt][0] * SCALING) : 0.f;
            float p1 = (c1 <= qi0 && qi0 - c1 < WINDOW) ? __expf(s[nt][1] * SCALING) : 0.f;
            float p2 = (c0 <= qi1 && qi1 - c0 < WINDOW) ? __expf(s[nt][2] * SCALING) : 0.f;
            float p3 = (c1 <= qi1 && qi1 - c1 < WINDOW) ? __expf(s[nt][3] * SCALING) : 0.f;
            l0 += p0 + p1;
            l1 += p2 + p3;
            s[nt][0] = p0; s[nt][1] = p1; s[nt][2] = p2; s[nt][3] = p3;
        }

        /* ---- O += P V (4 k-steps x 16 n-tiles, x3 split) ---- */
        #pragma unroll
        for (int ks = 0; ks < 4; ks++) {
            uint32_t ah0, al0, ah1, al1, ah2, al2, ah3, al3;
            split2(s[2*ks][0],   s[2*ks][1],   ah0, al0);
            split2(s[2*ks][2],   s[2*ks][3],   ah1, al1);
            split2(s[2*ks+1][0], s[2*ks+1][1], ah2, al2);
            split2(s[2*ks+1][2], s[2*ks+1][3], ah3, al3);
            #pragma unroll
            for (int nt = 0; nt < 16; nt++) {
                uint32_t bh0 = Vh[(ks * 8 + t4)     * VPAD + nt * 8 + g];
                uint32_t bh1 = Vh[(ks * 8 + t4 + 4) * VPAD + nt * 8 + g];
                uint32_t bl0 = Vl[(ks * 8 + t4)     * VPAD + nt * 8 + g];
                uint32_t bl1 = Vl[(ks * 8 + t4 + 4) * VPAD + nt * 8 + g];
                MMA_BF16(o[nt], ah0, ah1, ah2, ah3, bh0, bh1);
                MMA_BF16(o[nt], ah0, ah1, ah2, ah3, bl0, bl1);
                MMA_BF16(o[nt], al0, al1, al2, al3, bh0, bh1);
            }
        }
    }

    /* ---- reduce l across the 4 lanes sharing a row, add sink, normalize, store ---- */
    l0 += __shfl_xor_sync(0xffffffffu, l0, 1);
    l0 += __shfl_xor_sync(0xffffffffu, l0, 2);
    l1 += __shfl_xor_sync(0xffffffffu, l1, 1);
    l1 += __shfl_xor_sync(0xffffffffu, l1, 2);
    float sk = __expf(sink[h]);
    float inv0 = 1.0f / (l0 + sk);
    float inv1 = 1.0f / (l1 + sk);

    float* out0 = g_attn + (size_t)qi0 * QDIM + h * HD;
    float* out1 = g_attn + (size_t)qi1 * QDIM + h * HD;
    #pragma unroll
    for (int nt = 0; nt < 16; nt++) {
        int d = nt * 8 + 2 * t4;
        *(float2*)(out0 + d) = make_float2(o[nt][0] * inv0, o[nt][1] * inv0);
        *(float2*)(out1 + d) = make_float2(o[nt][2] * inv1, o[nt][3] * inv1);
    }
}

/* ------------------------- launch ------------------------- */
extern "C" void kernel_launch(void* const* d_in, const int* in_sizes, int n_in,
                              void* d_out, int out_size)
{
    const float* hs   = (const float*)d_in[0];
    const int*   pos  = (const int*)d_in[1];
    const float* wq   = (const float*)d_in[2];
    const float* wk   = (const float*)d_in[3];
    const float* wv   = (const float*)d_in[4];
    const float* wo   = (const float*)d_in[5];
    const float* sink = (const float*)d_in[6];
    float* out = (float*)d_out;

    float *q_ptr, *k_ptr, *v_ptr, *attn_ptr;
    cudaGetSymbolAddress((void**)&q_ptr, g_q);
    cudaGetSymbolAddress((void**)&k_ptr, g_k);
    cudaGetSymbolAddress((void**)&v_ptr, g_v);
    cudaGetSymbolAddress((void**)&attn_ptr, g_attn);

    /* QKV projections (tf32 tensor cores) */
    tf32_gemm_kernel<<<dim3(QDIM / GBN, SEQ / GBM), 256>>>(hs, wq, q_ptr, SEQ, QDIM, HIDDEN);
    tf32_gemm_kernel<<<dim3(KVDIM / GBN, SEQ / GBM), 256>>>(hs, wk, k_ptr, SEQ, KVDIM, HIDDEN);
    tf32_gemm_kernel<<<dim3(KVDIM / GBN, SEQ / GBM), 256>>>(hs, wv, v_ptr, SEQ, KVDIM, HIDDEN);

    /* RoPE */
    {
        int tq = SEQ * NQH * (HD / 2);
        rope_kernel<<<(tq + 255) / 256, 256>>>(q_ptr, pos, NQH);
        int tk = SEQ * NKVH * (HD / 2);
        rope_kernel<<<(tk + 255) / 256, 256>>>(k_ptr, pos, NKVH);
    }

    /* attention (bf16x3 tensor cores) */
    {
        int smem_words = 2 * AQT * KPAD + 2 * AKT * KPAD + 2 * (AKT/2) * VPAD;
        int smem = smem_words * 4;   /* 139264 B */
        cudaFuncSetAttribute(attn_mma_kernel, cudaFuncAttributeMaxDynamicSharedMemorySize, smem);
        attn_mma_kernel<<<dim3(SEQ / AQT, NQH), 256, smem>>>(sink);
    }

    /* output projection (tf32 tensor cores) */
    tf32_gemm_kernel<<<dim3(HIDDEN / GBN, SEQ / GBM), 256>>>(attn_ptr, wo, out, SEQ, HIDDEN, QDIM);
}

// round 5
// speedup vs baseline: 3.8694x; 1.2093x over previous
#include <cuda_runtime.h>
#include <cuda_bf16.h>
#include <math.h>
#include <stdint.h>

#define SEQ 2048
#define HIDDEN 4096
#define NQH 32
#define NKVH 8
#define HD 128
#define QDIM (NQH*HD)      /* 4096 */
#define KVDIM (NKVH*HD)    /* 1024 */
#define WINDOW 1024
#define SCALING 0.08838834764831845f  /* 128^-0.5 */

/* scratch (allocation-free rule: __device__ globals) */
__device__ float g_q[SEQ*QDIM];
__device__ float g_k[SEQ*KVDIM];
__device__ float g_v[SEQ*KVDIM];
__device__ float g_attn[SEQ*QDIM];

/* ------------------- TF32 tensor-core GEMM, 2-stage cp.async pipeline ------------------- */
/* C[M,N] = A[M,K] @ B[K,N], row-major. 128x128x32 CTA tile, 8 warps (64x32 warp tile),
   mma.m16n8k8.tf32. Raw fp32 staged via LDGSTS; cvt.rna at fragment load.                 */

#define GBM 128
#define GBN 128
#define GBK 32
#define ASTR 36     /* A smem row stride (floats) */
#define BSTR 136    /* B smem row stride (floats) */
#define A_STAGE (GBM*ASTR)   /* 4608 floats */
#define B_STAGE (GBK*BSTR)   /* 4352 floats */
#define GEMM_SMEM ((2*A_STAGE + 2*B_STAGE) * 4)   /* 71680 B */

__device__ __forceinline__ uint32_t f2tf32(float f) {
    uint32_t u;
    asm("cvt.rna.tf32.f32 %0, %1;" : "=r"(u) : "f"(f));
    return u;
}
__device__ __forceinline__ void cp_async16(float* smem_ptr, const float* gptr) {
    uint32_t s = (uint32_t)__cvta_generic_to_shared(smem_ptr);
    asm volatile("cp.async.cg.shared.global [%0], [%1], 16;" :: "r"(s), "l"(gptr));
}

__global__ __launch_bounds__(256, 2) void tf32_gemm_kernel(
    const float* __restrict__ A, const float* __restrict__ B, float* __restrict__ C,
    int M, int N, int K)
{
    extern __shared__ float sm[];
    float* As = sm;                    /* [2][GBM][ASTR] */
    float* Bs = sm + 2 * A_STAGE;      /* [2][GBK][BSTR] */

    const int tid  = threadIdx.x;
    const int lane = tid & 31;
    const int wid  = tid >> 5;
    const int wm   = (wid & 1) * 64;
    const int wn   = (wid >> 1) * 32;
    const int t4   = lane & 3;
    const int g    = lane >> 2;

    const int bm0 = blockIdx.y * GBM;
    const int bn0 = blockIdx.x * GBN;

    float acc[4][4][4];
    #pragma unroll
    for (int i = 0; i < 4; i++)
        #pragma unroll
        for (int j = 0; j < 4; j++)
            #pragma unroll
            for (int r = 0; r < 4; r++) acc[i][j][r] = 0.f;

    /* cp.async mappings: 4 chunks of 16B for A and 4 for B per thread per tile.
       A: 128 rows x 8 chunks (32 floats) = 1024 chunks; 2 threads/row, 4 chunks each. */
    const int ar = tid >> 1;             /* A row 0..127            */
    const int ac = (tid & 1) * 4;        /* chunk col base 0 or 4   */
    const int br = tid >> 5;             /* B row base 0..7 (step 8)*/
    const int bc = tid & 31;             /* B chunk col 0..31       */

    const int T = K / GBK;

    /* prologue: stage tile 0 into buffer 0 */
    {
        const float* Ag = A + (size_t)(bm0 + ar) * K;
        #pragma unroll
        for (int s = 0; s < 4; s++)
            cp_async16(&As[ar * ASTR + (ac + s) * 4], Ag + (ac + s) * 4);
        #pragma unroll
        for (int s = 0; s < 4; s++)
            cp_async16(&Bs[(br + s * 8) * BSTR + bc * 4],
                       B + (size_t)(br + s * 8) * N + bn0 + bc * 4);
        asm volatile("cp.async.commit_group;");
    }

    for (int t = 0; t < T; t++) {
        const int buf = t & 1;
        if (t + 1 < T) {
            const int nb = (t + 1) & 1;
            const int k0 = (t + 1) * GBK;
            const float* Ag = A + (size_t)(bm0 + ar) * K + k0;
            #pragma unroll
            for (int s = 0; s < 4; s++)
                cp_async16(&As[nb * A_STAGE + ar * ASTR + (ac + s) * 4], Ag + (ac + s) * 4);
            #pragma unroll
            for (int s = 0; s < 4; s++)
                cp_async16(&Bs[nb * B_STAGE + (br + s * 8) * BSTR + bc * 4],
                           B + (size_t)(k0 + br + s * 8) * N + bn0 + bc * 4);
            asm volatile("cp.async.commit_group;");
            asm volatile("cp.async.wait_group 1;");
        } else {
            asm volatile("cp.async.wait_group 0;");
        }
        __syncthreads();

        const float* Ab = As + buf * A_STAGE;
        const float* Bb = Bs + buf * B_STAGE;

        #pragma unroll
        for (int ks = 0; ks < 4; ks++) {
            const int kk = ks * 8;
            uint32_t a[4][4], b[4][2];
            #pragma unroll
            for (int i = 0; i < 4; i++) {
                const int mr = wm + i * 16 + g;
                a[i][0] = f2tf32(Ab[mr * ASTR + kk + t4]);
                a[i][1] = f2tf32(Ab[(mr + 8) * ASTR + kk + t4]);
                a[i][2] = f2tf32(Ab[mr * ASTR + kk + t4 + 4]);
                a[i][3] = f2tf32(Ab[(mr + 8) * ASTR + kk + t4 + 4]);
            }
            #pragma unroll
            for (int j = 0; j < 4; j++) {
                const int nc = wn + j * 8 + g;
                b[j][0] = f2tf32(Bb[(kk + t4) * BSTR + nc]);
                b[j][1] = f2tf32(Bb[(kk + t4 + 4) * BSTR + nc]);
            }
            #pragma unroll
            for (int i = 0; i < 4; i++)
                #pragma unroll
                for (int j = 0; j < 4; j++) {
                    asm volatile(
                        "mma.sync.aligned.m16n8k8.row.col.f32.tf32.tf32.f32 "
                        "{%0,%1,%2,%3}, {%4,%5,%6,%7}, {%8,%9}, {%0,%1,%2,%3};"
                        : "+f"(acc[i][j][0]), "+f"(acc[i][j][1]),
                          "+f"(acc[i][j][2]), "+f"(acc[i][j][3])
                        : "r"(a[i][0]), "r"(a[i][1]), "r"(a[i][2]), "r"(a[i][3]),
                          "r"(b[j][0]), "r"(b[j][1]));
                }
        }
        __syncthreads();
    }

    #pragma unroll
    for (int i = 0; i < 4; i++) {
        int row0 = bm0 + wm + i * 16 + g;
        #pragma unroll
        for (int j = 0; j < 4; j++) {
            int col = bn0 + wn + j * 8 + 2 * t4;
            *(float2*)(C + (size_t)row0 * N + col)       = make_float2(acc[i][j][0], acc[i][j][1]);
            *(float2*)(C + (size_t)(row0 + 8) * N + col) = make_float2(acc[i][j][2], acc[i][j][3]);
        }
    }
}

/* ------------------------- RoPE (NeoX) ------------------------- */
__global__ void rope_kernel(float* x, const int* __restrict__ positions, int nheads)
{
    int idx = blockIdx.x * blockDim.x + threadIdx.x;
    int total = SEQ * nheads * (HD / 2);
    if (idx >= total) return;
    int i = idx & 63;
    int h = (idx >> 6) % nheads;
    int s = idx / (64 * nheads);
    float inv = powf(1000000.0f, -(float)i * (1.0f / 64.0f));
    float f = (float)positions[s] * inv;
    float c = cosf(f), sn = sinf(f);
    float* base = x + ((size_t)s * nheads + h) * HD;
    float x1 = base[i], x2 = base[i + 64];
    base[i]      = x1 * c - x2 * sn;
    base[i + 64] = x2 * c + x1 * sn;
}

/* ------------------------- Attention: bf16x3 tensor-core flash (unchanged, passing) ---- */
#define AQT 128
#define AKT 64
#define KPAD 68
#define VPAD 136

#define MMA_BF16(c, a0,a1,a2,a3, b0,b1)                                      \
    asm volatile("mma.sync.aligned.m16n8k16.row.col.f32.bf16.bf16.f32 "      \
        "{%0,%1,%2,%3}, {%4,%5,%6,%7}, {%8,%9}, {%0,%1,%2,%3};"              \
        : "+f"(c[0]), "+f"(c[1]), "+f"(c[2]), "+f"(c[3])                     \
        : "r"(a0), "r"(a1), "r"(a2), "r"(a3), "r"(b0), "r"(b1))

__device__ __forceinline__ void split2(float x, float y, uint32_t& hi, uint32_t& lo) {
    __nv_bfloat162 h = __float22bfloat162_rn(make_float2(x, y));
    float rx = x - __bfloat162float(h.x);
    float ry = y - __bfloat162float(h.y);
    __nv_bfloat162 l = __float22bfloat162_rn(make_float2(rx, ry));
    hi = *(uint32_t*)&h;
    lo = *(uint32_t*)&l;
}

__global__ __launch_bounds__(256, 1) void attn_mma_kernel(const float* __restrict__ sink)
{
    extern __shared__ uint32_t smw[];
    uint32_t* Qh = smw;
    uint32_t* Ql = Qh + AQT * KPAD;
    uint32_t* Kh = Ql + AQT * KPAD;
    uint32_t* Kl = Kh + AKT * KPAD;
    uint32_t* Vh = Kl + AKT * KPAD;
    uint32_t* Vl = Vh + (AKT/2) * VPAD;

    const int h   = blockIdx.y;
    const int q0  = blockIdx.x * AQT;
    const int kvh = h >> 2;
    const int tid = threadIdx.x;
    const int lane = tid & 31;
    const int wid  = tid >> 5;
    const int wrow = wid * 16;
    const int t4   = lane & 3;
    const int g    = lane >> 2;

    {
        const float* Qg = g_q + (size_t)q0 * QDIM + h * HD;
        #pragma unroll
        for (int it = 0; it < 16; it++) {
            int slot = tid + it * 256;
            int r = slot >> 5, d4 = slot & 31;
            float4 v = *(const float4*)(Qg + (size_t)r * QDIM + d4 * 4);
            uint32_t h01, l01, h23, l23;
            split2(v.x, v.y, h01, l01);
            split2(v.z, v.w, h23, l23);
            Qh[r * KPAD + d4 * 2]     = h01;
            Qh[r * KPAD + d4 * 2 + 1] = h23;
            Ql[r * KPAD + d4 * 2]     = l01;
            Ql[r * KPAD + d4 * 2 + 1] = l23;
        }
    }

    float o[16][4];
    #pragma unroll
    for (int i = 0; i < 16; i++)
        #pragma unroll
        for (int r = 0; r < 4; r++) o[i][r] = 0.f;
    float l0 = 0.f, l1 = 0.f;

    int jlo = q0 - (WINDOW - 1);
    if (jlo < 0) jlo = 0;
    int kt0 = (jlo / AKT) * AKT;

    const int qi0 = q0 + wrow + g;
    const int qi1 = qi0 + 8;

    for (int kt = kt0; kt < q0 + AQT; kt += AKT) {
        __syncthreads();
        {
            const float* Kg = g_k + (size_t)kt * KVDIM + kvh * HD;
            #pragma unroll
            for (int it = 0; it < 8; it++) {
                int slot = tid + it * 256;
                int r = slot >> 5, d4 = slot & 31;
                float4 v = *(const float4*)(Kg + (size_t)r * KVDIM + d4 * 4);
                uint32_t h01, l01, h23, l23;
                split2(v.x, v.y, h01, l01);
                split2(v.z, v.w, h23, l23);
                Kh[r * KPAD + d4 * 2]     = h01;
                Kh[r * KPAD + d4 * 2 + 1] = h23;
                Kl[r * KPAD + d4 * 2]     = l01;
                Kl[r * KPAD + d4 * 2 + 1] = l23;
            }
        }
        {
            const float* Vg = g_v + (size_t)kt * KVDIM + kvh * HD;
            #pragma unroll
            for (int it = 0; it < 4; it++) {
                int slot = tid + it * 256;
                int rp = slot >> 5, d4 = slot & 31;
                float4 v0 = *(const float4*)(Vg + (size_t)(2 * rp) * KVDIM + d4 * 4);
                float4 v1 = *(const float4*)(Vg + (size_t)(2 * rp + 1) * KVDIM + d4 * 4);
                const float* a = &v0.x;
                const float* b = &v1.x;
                #pragma unroll
                for (int jj = 0; jj < 4; jj++) {
                    uint32_t hi, lo;
                    split2(a[jj], b[jj], hi, lo);
                    Vh[rp * VPAD + d4 * 4 + jj] = hi;
                    Vl[rp * VPAD + d4 * 4 + jj] = lo;
                }
            }
        }
        __syncthreads();

        float s[8][4];
        #pragma unroll
        for (int nt = 0; nt < 8; nt++)
            #pragma unroll
            for (int r = 0; r < 4; r++) s[nt][r] = 0.f;

        #pragma unroll
        for (int kk = 0; kk < 8; kk++) {
            const int kw = kk * 8;
            uint32_t ah0 = Qh[(wrow + g)     * KPAD + kw + t4];
            uint32_t ah1 = Qh[(wrow + g + 8) * KPAD + kw + t4];
            uint32_t ah2 = Qh[(wrow + g)     * KPAD + kw + t4 + 4];
            uint32_t ah3 = Qh[(wrow + g + 8) * KPAD + kw + t4 + 4];
            uint32_t al0 = Ql[(wrow + g)     * KPAD + kw + t4];
            uint32_t al1 = Ql[(wrow + g + 8) * KPAD + kw + t4];
            uint32_t al2 = Ql[(wrow + g)     * KPAD + kw + t4 + 4];
            uint32_t al3 = Ql[(wrow + g + 8) * KPAD + kw + t4 + 4];
            #pragma unroll
            for (int nt = 0; nt < 8; nt++) {
                const int krow = nt * 8 + g;
                uint32_t bh0 = Kh[krow * KPAD + kw + t4];
                uint32_t bh1 = Kh[krow * KPAD + kw + t4 + 4];
                uint32_t bl0 = Kl[krow * KPAD + kw + t4];
                uint32_t bl1 = Kl[krow * KPAD + kw + t4 + 4];
                MMA_BF16(s[nt], ah0, ah1, ah2, ah3, bh0, bh1);
                MMA_BF16(s[nt], ah0, ah1, ah2, ah3, bl0, bl1);
                MMA_BF16(s[nt], al0, al1, al2, al3, bh0, bh1);
            }
        }

        #pragma unroll
        for (int nt = 0; nt < 8; nt++) {
            int c0 = kt + nt * 8 + 2 * t4;
            int c1 = c0 + 1;
            float p0 = (c0 <= qi0 && qi0 - c0 < WINDOW) ? __expf(s[nt][0] * SCALING) : 0.f;
            float p1 = (c1 <= qi0 && qi0 - c1 < WINDOW) ? __expf(s[nt][1] * SCALING) : 0.f;
            float p2 = (c0 <= qi1 && qi1 - c0 < WINDOW) ? __expf(s[nt][2] * SCALING) : 0.f;
            float p3 = (c1 <= qi1 && qi1 - c1 < WINDOW) ? __expf(s[nt][3] * SCALING) : 0.f;
            l0 += p0 + p1;
            l1 += p2 + p3;
            s[nt][0] = p0; s[nt][1] = p1; s[nt][2] = p2; s[nt][3] = p3;
        }

        #pragma unroll
        for (int ks = 0; ks < 4; ks++) {
            uint32_t ah0, al0, ah1, al1, ah2, al2, ah3, al3;
            split2(s[2*ks][0],   s[2*ks][1],   ah0, al0);
            split2(s[2*ks][2],   s[2*ks][3],   ah1, al1);
            split2(s[2*ks+1][0], s[2*ks+1][1], ah2, al2);
            split2(s[2*ks+1][2], s[2*ks+1][3], ah3, al3);
            #pragma unroll
            for (int nt = 0; nt < 16; nt++) {
                uint32_t bh0 = Vh[(ks * 8 + t4)     * VPAD + nt * 8 + g];
                uint32_t bh1 = Vh[(ks * 8 + t4 + 4) * VPAD + nt * 8 + g];
                uint32_t bl0 = Vl[(ks * 8 + t4)     * VPAD + nt * 8 + g];
                uint32_t bl1 = Vl[(ks * 8 + t4 + 4) * VPAD + nt * 8 + g];
                MMA_BF16(o[nt], ah0, ah1, ah2, ah3, bh0, bh1);
                MMA_BF16(o[nt], ah0, ah1, ah2, ah3, bl0, bl1);
                MMA_BF16(o[nt], al0, al1, al2, al3, bh0, bh1);
            }
        }
    }

    l0 += __shfl_xor_sync(0xffffffffu, l0, 1);
    l0 += __shfl_xor_sync(0xffffffffu, l0, 2);
    l1 += __shfl_xor_sync(0xffffffffu, l1, 1);
    l1 += __shfl_xor_sync(0xffffffffu, l1, 2);
    float sk = __expf(sink[h]);
    float inv0 = 1.0f / (l0 + sk);
    float inv1 = 1.0f / (l1 + sk);

    float* out0 = g_attn + (size_t)qi0 * QDIM + h * HD;
    float* out1 = g_attn + (size_t)qi1 * QDIM + h * HD;
    #pragma unroll
    for (int nt = 0; nt < 16; nt++) {
        int d = nt * 8 + 2 * t4;
        *(float2*)(out0 + d) = make_float2(o[nt][0] * inv0, o[nt][1] * inv0);
        *(float2*)(out1 + d) = make_float2(o[nt][2] * inv1, o[nt][3] * inv1);
    }
}

/* ------------------------- launch ------------------------- */
extern "C" void kernel_launch(void* const* d_in, const int* in_sizes, int n_in,
                              void* d_out, int out_size)
{
    const float* hs   = (const float*)d_in[0];
    const int*   pos  = (const int*)d_in[1];
    const float* wq   = (const float*)d_in[2];
    const float* wk   = (const float*)d_in[3];
    const float* wv   = (const float*)d_in[4];
    const float* wo   = (const float*)d_in[5];
    const float* sink = (const float*)d_in[6];
    float* out = (float*)d_out;

    float *q_ptr, *k_ptr, *v_ptr, *attn_ptr;
    cudaGetSymbolAddress((void**)&q_ptr, g_q);
    cudaGetSymbolAddress((void**)&k_ptr, g_k);
    cudaGetSymbolAddress((void**)&v_ptr, g_v);
    cudaGetSymbolAddress((void**)&attn_ptr, g_attn);

    cudaFuncSetAttribute(tf32_gemm_kernel, cudaFuncAttributeMaxDynamicSharedMemorySize, GEMM_SMEM);

    /* QKV projections (tf32 tensor cores, pipelined) */
    tf32_gemm_kernel<<<dim3(QDIM / GBN, SEQ / GBM), 256, GEMM_SMEM>>>(hs, wq, q_ptr, SEQ, QDIM, HIDDEN);
    tf32_gemm_kernel<<<dim3(KVDIM / GBN, SEQ / GBM), 256, GEMM_SMEM>>>(hs, wk, k_ptr, SEQ, KVDIM, HIDDEN);
    tf32_gemm_kernel<<<dim3(KVDIM / GBN, SEQ / GBM), 256, GEMM_SMEM>>>(hs, wv, v_ptr, SEQ, KVDIM, HIDDEN);

    /* RoPE */
    {
        int tq = SEQ * NQH * (HD / 2);
        rope_kernel<<<(tq + 255) / 256, 256>>>(q_ptr, pos, NQH);
        int tk = SEQ * NKVH * (HD / 2);
        rope_kernel<<<(tk + 255) / 256, 256>>>(k_ptr, pos, NKVH);
    }

    /* attention (bf16x3 tensor cores) */
    {
        int smem_words = 2 * AQT * KPAD + 2 * AKT * KPAD + 2 * (AKT/2) * VPAD;
        int smem = smem_words * 4;
        cudaFuncSetAttribute(attn_mma_kernel, cudaFuncAttributeMaxDynamicSharedMemorySize, smem);
        attn_mma_kernel<<<dim3(SEQ / AQT, NQH), 256, smem>>>(sink);
    }

    /* output projection */
    tf32_gemm_kernel<<<dim3(HIDDEN / GBN, SEQ / GBM), 256, GEMM_SMEM>>>(attn_ptr, wo, out, SEQ, HIDDEN, QDIM);
}

// round 6
// speedup vs baseline: 4.6012x; 1.1891x over previous
#include <cuda_runtime.h>
#include <cuda_bf16.h>
#include <math.h>
#include <stdint.h>

#define SEQ 2048
#define HIDDEN 4096
#define NQH 32
#define NKVH 8
#define HD 128
#define QDIM (NQH*HD)      /* 4096 */
#define KVDIM (NKVH*HD)    /* 1024 */
#define WINDOW 1024
#define SCALING 0.08838834764831845f  /* 128^-0.5 */

/* scratch (allocation-free rule: __device__ globals) */
__device__ float g_q[SEQ*QDIM];
__device__ float g_k[SEQ*KVDIM];
__device__ float g_v[SEQ*KVDIM];
__device__ float g_attn[SEQ*QDIM];
/* tf32-pre-rounded GEMM operands */
__device__ float g_hs[SEQ*HIDDEN];
__device__ float g_wq[HIDDEN*QDIM];
__device__ float g_wk[HIDDEN*KVDIM];
__device__ float g_wv[HIDDEN*KVDIM];
__device__ float g_wo[QDIM*HIDDEN];

__device__ __forceinline__ float roundtf(float x) {
    float r;
    asm("cvt.rna.tf32.f32 %0, %1;" : "=f"(r) : "f"(x));
    return r;
}

/* elementwise tf32 rounding pass (float4 vectorized; sizes are multiples of 1024) */
__global__ void round_tf32_kernel(const float* __restrict__ in, float* __restrict__ out, int n4)
{
    int i = blockIdx.x * blockDim.x + threadIdx.x;
    if (i >= n4) return;
    float4 v = ((const float4*)in)[i];
    v.x = roundtf(v.x); v.y = roundtf(v.y);
    v.z = roundtf(v.z); v.w = roundtf(v.w);
    ((float4*)out)[i] = v;
}

/* ---------------- TF32 GEMM: 128x256 CTA, 8 warps 64x64, 3-stage cp.async ---------------- */
/* Inputs MUST be tf32-pre-rounded fp32 (mma reads raw bits; truncation == identity).        */

#define GBM 128
#define GBN 256
#define GBK 32
#define ASTR 36                    /* floats */
#define BSTR 264                   /* floats; 264 mod 32 = 8 */
#define A_STAGE (GBM*ASTR)         /* 4608  */
#define B_STAGE (GBK*BSTR)         /* 8448  */
#define STG 3
#define GEMM_SMEM (STG*(A_STAGE+B_STAGE)*4)   /* 156672 B */

__device__ __forceinline__ void cp_async16(float* smem_ptr, const float* gptr) {
    uint32_t s = (uint32_t)__cvta_generic_to_shared(smem_ptr);
    asm volatile("cp.async.cg.shared.global [%0], [%1], 16;" :: "r"(s), "l"(gptr));
}

__device__ __forceinline__ void gemm_body(
    const float* __restrict__ A, const float* __restrict__ B, float* __restrict__ C,
    int ldb, int ldc, int K, int bm0, int bn0, float* sm)
{
    float* As = sm;                    /* [STG][128][ASTR] */
    float* Bs = sm + STG * A_STAGE;    /* [STG][32][BSTR]  */

    const int tid  = threadIdx.x;
    const int lane = tid & 31;
    const int wid  = tid >> 5;
    const int wm   = (wid & 1) * 64;
    const int wn   = (wid >> 1) * 64;
    const int t4   = lane & 3;
    const int g    = lane >> 2;

    float acc[4][8][4];
    #pragma unroll
    for (int i = 0; i < 4; i++)
        #pragma unroll
        for (int j = 0; j < 8; j++)
            #pragma unroll
            for (int r = 0; r < 4; r++) acc[i][j][r] = 0.f;

    /* staging maps: A 1024 chunks (4/thread), B 2048 chunks (8/thread) */
    const int ar = tid >> 1;         /* 0..127 */
    const int ac = (tid & 1) * 4;    /* chunk base 0 or 4 (of 8) */
    const int br = tid >> 3;         /* 0..31  */
    const int bc = tid & 7;          /* 0..7   */

    const int T = K / GBK;

    #define STAGE_TILE(ti, buf) do {                                              \
        const int _k0 = (ti) * GBK;                                               \
        const float* _Ag = A + (size_t)(bm0 + ar) * K + _k0;                      \
        _Pragma("unroll")                                                         \
        for (int s = 0; s < 4; s++)                                               \
            cp_async16(&As[(buf)*A_STAGE + ar*ASTR + (ac + s)*4], _Ag + (ac + s)*4);\
        const float* _Bg = B + (size_t)(_k0 + br) * ldb + bn0;                    \
        _Pragma("unroll")                                                         \
        for (int s = 0; s < 8; s++)                                               \
            cp_async16(&Bs[(buf)*B_STAGE + br*BSTR + (bc + s*8)*4], _Bg + (bc + s*8)*4);\
    } while (0)

    STAGE_TILE(0, 0);
    asm volatile("cp.async.commit_group;");
    STAGE_TILE(1, 1);
    asm volatile("cp.async.commit_group;");

    int buf = 0;
    for (int t = 0; t < T; t++) {
        if (t + 2 < T) {
            int nb = buf - 1; if (nb < 0) nb += STG;   /* (t+2) % STG */
            STAGE_TILE(t + 2, nb);
        }
        asm volatile("cp.async.commit_group;");   /* uniform group count (may be empty) */
        asm volatile("cp.async.wait_group 2;");   /* groups <= t complete */
        __syncthreads();

        const uint32_t* Ab = (const uint32_t*)(As + buf * A_STAGE);
        const uint32_t* Bb = (const uint32_t*)(Bs + buf * B_STAGE);

        #pragma unroll
        for (int ks = 0; ks < 4; ks++) {
            const int kk = ks * 8;
            uint32_t a[4][4], b[8][2];
            #pragma unroll
            for (int i = 0; i < 4; i++) {
                const int mr = wm + i * 16 + g;
                a[i][0] = Ab[mr * ASTR + kk + t4];
                a[i][1] = Ab[(mr + 8) * ASTR + kk + t4];
                a[i][2] = Ab[mr * ASTR + kk + t4 + 4];
                a[i][3] = Ab[(mr + 8) * ASTR + kk + t4 + 4];
            }
            #pragma unroll
            for (int j = 0; j < 8; j++) {
                const int nc = wn + j * 8 + g;
                b[j][0] = Bb[(kk + t4) * BSTR + nc];
                b[j][1] = Bb[(kk + t4 + 4) * BSTR + nc];
            }
            #pragma unroll
            for (int i = 0; i < 4; i++)
                #pragma unroll
                for (int j = 0; j < 8; j++) {
                    asm volatile(
                        "mma.sync.aligned.m16n8k8.row.col.f32.tf32.tf32.f32 "
                        "{%0,%1,%2,%3}, {%4,%5,%6,%7}, {%8,%9}, {%0,%1,%2,%3};"
                        : "+f"(acc[i][j][0]), "+f"(acc[i][j][1]),
                          "+f"(acc[i][j][2]), "+f"(acc[i][j][3])
                        : "r"(a[i][0]), "r"(a[i][1]), "r"(a[i][2]), "r"(a[i][3]),
                          "r"(b[j][0]), "r"(b[j][1]));
                }
        }
        __syncthreads();
        buf++; if (buf == STG) buf = 0;
    }
    #undef STAGE_TILE

    #pragma unroll
    for (int i = 0; i < 4; i++) {
        int row0 = bm0 + wm + i * 16 + g;
        #pragma unroll
        for (int j = 0; j < 8; j++) {
            int col = bn0 + wn + j * 8 + 2 * t4;
            *(float2*)(C + (size_t)row0 * ldc + col)       = make_float2(acc[i][j][0], acc[i][j][1]);
            *(float2*)(C + (size_t)(row0 + 8) * ldc + col) = make_float2(acc[i][j][2], acc[i][j][3]);
        }
    }
}

/* fused QKV: grid.x = 24 (16 Q cols + 4 K + 4 V), grid.y = 16 */
__global__ __launch_bounds__(256, 1) void qkv_gemm_kernel()
{
    extern __shared__ float sm[];
    const int bx = blockIdx.x;
    const int bm0 = blockIdx.y * GBM;
    if (bx < 16)
        gemm_body(g_hs, g_wq, g_q, QDIM, QDIM, HIDDEN, bm0, bx * GBN, sm);
    else if (bx < 20)
        gemm_body(g_hs, g_wk, g_k, KVDIM, KVDIM, HIDDEN, bm0, (bx - 16) * GBN, sm);
    else
        gemm_body(g_hs, g_wv, g_v, KVDIM, KVDIM, HIDDEN, bm0, (bx - 20) * GBN, sm);
}

__global__ __launch_bounds__(256, 1) void o_gemm_kernel(float* __restrict__ out)
{
    extern __shared__ float sm[];
    gemm_body(g_attn, g_wo, out, HIDDEN, HIDDEN, QDIM, blockIdx.y * GBM, blockIdx.x * GBN, sm);
}

/* ------------------------- RoPE (NeoX) ------------------------- */
__global__ void rope_kernel(float* x, const int* __restrict__ positions, int nheads)
{
    int idx = blockIdx.x * blockDim.x + threadIdx.x;
    int total = SEQ * nheads * (HD / 2);
    if (idx >= total) return;
    int i = idx & 63;
    int h = (idx >> 6) % nheads;
    int s = idx / (64 * nheads);
    float inv = powf(1000000.0f, -(float)i * (1.0f / 64.0f));
    float f = (float)positions[s] * inv;
    float c = cosf(f), sn = sinf(f);
    float* base = x + ((size_t)s * nheads + h) * HD;
    float x1 = base[i], x2 = base[i + 64];
    base[i]      = x1 * c - x2 * sn;
    base[i + 64] = x2 * c + x1 * sn;
}

/* ------------------------- Attention: bf16x3 tensor-core flash ------------------------- */
#define AQT 128
#define AKT 64
#define KPAD 68
#define VPAD 136

#define MMA_BF16(c, a0,a1,a2,a3, b0,b1)                                      \
    asm volatile("mma.sync.aligned.m16n8k16.row.col.f32.bf16.bf16.f32 "      \
        "{%0,%1,%2,%3}, {%4,%5,%6,%7}, {%8,%9}, {%0,%1,%2,%3};"              \
        : "+f"(c[0]), "+f"(c[1]), "+f"(c[2]), "+f"(c[3])                     \
        : "r"(a0), "r"(a1), "r"(a2), "r"(a3), "r"(b0), "r"(b1))

__device__ __forceinline__ void split2(float x, float y, uint32_t& hi, uint32_t& lo) {
    __nv_bfloat162 h = __float22bfloat162_rn(make_float2(x, y));
    float rx = x - __bfloat162float(h.x);
    float ry = y - __bfloat162float(h.y);
    __nv_bfloat162 l = __float22bfloat162_rn(make_float2(rx, ry));
    hi = *(uint32_t*)&h;
    lo = *(uint32_t*)&l;
}

__global__ __launch_bounds__(256, 1) void attn_mma_kernel(const float* __restrict__ sink)
{
    extern __shared__ uint32_t smw[];
    uint32_t* Qh = smw;
    uint32_t* Ql = Qh + AQT * KPAD;
    uint32_t* Kh = Ql + AQT * KPAD;
    uint32_t* Kl = Kh + AKT * KPAD;
    uint32_t* Vh = Kl + AKT * KPAD;
    uint32_t* Vl = Vh + (AKT/2) * VPAD;

    const int h   = blockIdx.y;
    const int q0  = blockIdx.x * AQT;
    const int kvh = h >> 2;
    const int tid = threadIdx.x;
    const int lane = tid & 31;
    const int wid  = tid >> 5;
    const int wrow = wid * 16;
    const int t4   = lane & 3;
    const int g    = lane >> 2;

    {
        const float* Qg = g_q + (size_t)q0 * QDIM + h * HD;
        #pragma unroll
        for (int it = 0; it < 16; it++) {
            int slot = tid + it * 256;
            int r = slot >> 5, d4 = slot & 31;
            float4 v = *(const float4*)(Qg + (size_t)r * QDIM + d4 * 4);
            uint32_t h01, l01, h23, l23;
            split2(v.x, v.y, h01, l01);
            split2(v.z, v.w, h23, l23);
            Qh[r * KPAD + d4 * 2]     = h01;
            Qh[r * KPAD + d4 * 2 + 1] = h23;
            Ql[r * KPAD + d4 * 2]     = l01;
            Ql[r * KPAD + d4 * 2 + 1] = l23;
        }
    }

    float o[16][4];
    #pragma unroll
    for (int i = 0; i < 16; i++)
        #pragma unroll
        for (int r = 0; r < 4; r++) o[i][r] = 0.f;
    float l0 = 0.f, l1 = 0.f;

    int jlo = q0 - (WINDOW - 1);
    if (jlo < 0) jlo = 0;
    int kt0 = (jlo / AKT) * AKT;

    const int qi0 = q0 + wrow + g;
    const int qi1 = qi0 + 8;

    for (int kt = kt0; kt < q0 + AQT; kt += AKT) {
        __syncthreads();
        {
            const float* Kg = g_k + (size_t)kt * KVDIM + kvh * HD;
            #pragma unroll
            for (int it = 0; it < 8; it++) {
                int slot = tid + it * 256;
                int r = slot >> 5, d4 = slot & 31;
                float4 v = *(const float4*)(Kg + (size_t)r * KVDIM + d4 * 4);
                uint32_t h01, l01, h23, l23;
                split2(v.x, v.y, h01, l01);
                split2(v.z, v.w, h23, l23);
                Kh[r * KPAD + d4 * 2]     = h01;
                Kh[r * KPAD + d4 * 2 + 1] = h23;
                Kl[r * KPAD + d4 * 2]     = l01;
                Kl[r * KPAD + d4 * 2 + 1] = l23;
            }
        }
        {
            const float* Vg = g_v + (size_t)kt * KVDIM + kvh * HD;
            #pragma unroll
            for (int it = 0; it < 4; it++) {
                int slot = tid + it * 256;
                int rp = slot >> 5, d4 = slot & 31;
                float4 v0 = *(const float4*)(Vg + (size_t)(2 * rp) * KVDIM + d4 * 4);
                float4 v1 = *(const float4*)(Vg + (size_t)(2 * rp + 1) * KVDIM + d4 * 4);
                const float* a = &v0.x;
                const float* b = &v1.x;
                #pragma unroll
                for (int jj = 0; jj < 4; jj++) {
                    uint32_t hi, lo;
                    split2(a[jj], b[jj], hi, lo);
                    Vh[rp * VPAD + d4 * 4 + jj] = hi;
                    Vl[rp * VPAD + d4 * 4 + jj] = lo;
                }
            }
        }
        __syncthreads();

        float s[8][4];
        #pragma unroll
        for (int nt = 0; nt < 8; nt++)
            #pragma unroll
            for (int r = 0; r < 4; r++) s[nt][r] = 0.f;

        #pragma unroll
        for (int kk = 0; kk < 8; kk++) {
            const int kw = kk * 8;
            uint32_t ah0 = Qh[(wrow + g)     * KPAD + kw + t4];
            uint32_t ah1 = Qh[(wrow + g + 8) * KPAD + kw + t4];
            uint32_t ah2 = Qh[(wrow + g)     * KPAD + kw + t4 + 4];
            uint32_t ah3 = Qh[(wrow + g + 8) * KPAD + kw + t4 + 4];
            uint32_t al0 = Ql[(wrow + g)     * KPAD + kw + t4];
            uint32_t al1 = Ql[(wrow + g + 8) * KPAD + kw + t4];
            uint32_t al2 = Ql[(wrow + g)     * KPAD + kw + t4 + 4];
            uint32_t al3 = Ql[(wrow + g + 8) * KPAD + kw + t4 + 4];
            #pragma unroll
            for (int nt = 0; nt < 8; nt++) {
                const int krow = nt * 8 + g;
                uint32_t bh0 = Kh[krow * KPAD + kw + t4];
                uint32_t bh1 = Kh[krow * KPAD + kw + t4 + 4];
                uint32_t bl0 = Kl[krow * KPAD + kw + t4];
                uint32_t bl1 = Kl[krow * KPAD + kw + t4 + 4];
                MMA_BF16(s[nt], ah0, ah1, ah2, ah3, bh0, bh1);
                MMA_BF16(s[nt], ah0, ah1, ah2, ah3, bl0, bl1);
                MMA_BF16(s[nt], al0, al1, al2, al3, bh0, bh1);
            }
        }

        #pragma unroll
        for (int nt = 0; nt < 8; nt++) {
            int c0 = kt + nt * 8 + 2 * t4;
            int c1 = c0 + 1;
            float p0 = (c0 <= qi0 && qi0 - c0 < WINDOW) ? __expf(s[nt][0] * SCALING) : 0.f;
            float p1 = (c1 <= qi0 && qi0 - c1 < WINDOW) ? __expf(s[nt][1] * SCALING) : 0.f;
            float p2 = (c0 <= qi1 && qi1 - c0 < WINDOW) ? __expf(s[nt][2] * SCALING) : 0.f;
            float p3 = (c1 <= qi1 && qi1 - c1 < WINDOW) ? __expf(s[nt][3] * SCALING) : 0.f;
            l0 += p0 + p1;
            l1 += p2 + p3;
            s[nt][0] = p0; s[nt][1] = p1; s[nt][2] = p2; s[nt][3] = p3;
        }

        #pragma unroll
        for (int ks = 0; ks < 4; ks++) {
            uint32_t ah0, al0, ah1, al1, ah2, al2, ah3, al3;
            split2(s[2*ks][0],   s[2*ks][1],   ah0, al0);
            split2(s[2*ks][2],   s[2*ks][3],   ah1, al1);
            split2(s[2*ks+1][0], s[2*ks+1][1], ah2, al2);
            split2(s[2*ks+1][2], s[2*ks+1][3], ah3, al3);
            #pragma unroll
            for (int nt = 0; nt < 16; nt++) {
                uint32_t bh0 = Vh[(ks * 8 + t4)     * VPAD + nt * 8 + g];
                uint32_t bh1 = Vh[(ks * 8 + t4 + 4) * VPAD + nt * 8 + g];
                uint32_t bl0 = Vl[(ks * 8 + t4)     * VPAD + nt * 8 + g];
                uint32_t bl1 = Vl[(ks * 8 + t4 + 4) * VPAD + nt * 8 + g];
                MMA_BF16(o[nt], ah0, ah1, ah2, ah3, bh0, bh1);
                MMA_BF16(o[nt], ah0, ah1, ah2, ah3, bl0, bl1);
                MMA_BF16(o[nt], al0, al1, al2, al3, bh0, bh1);
            }
        }
    }

    l0 += __shfl_xor_sync(0xffffffffu, l0, 1);
    l0 += __shfl_xor_sync(0xffffffffu, l0, 2);
    l1 += __shfl_xor_sync(0xffffffffu, l1, 1);
    l1 += __shfl_xor_sync(0xffffffffu, l1, 2);
    float sk = __expf(sink[h]);
    float inv0 = 1.0f / (l0 + sk);
    float inv1 = 1.0f / (l1 + sk);

    /* store tf32-rounded so the O-projection GEMM can consume raw bits */
    float* out0 = g_attn + (size_t)qi0 * QDIM + h * HD;
    float* out1 = g_attn + (size_t)qi1 * QDIM + h * HD;
    #pragma unroll
    for (int nt = 0; nt < 16; nt++) {
        int d = nt * 8 + 2 * t4;
        *(float2*)(out0 + d) = make_float2(roundtf(o[nt][0] * inv0), roundtf(o[nt][1] * inv0));
        *(float2*)(out1 + d) = make_float2(roundtf(o[nt][2] * inv1), roundtf(o[nt][3] * inv1));
    }
}

/* ------------------------- launch ------------------------- */
extern "C" void kernel_launch(void* const* d_in, const int* in_sizes, int n_in,
                              void* d_out, int out_size)
{
    const float* hs   = (const float*)d_in[0];
    const int*   pos  = (const int*)d_in[1];
    const float* wq   = (const float*)d_in[2];
    const float* wk   = (const float*)d_in[3];
    const float* wv   = (const float*)d_in[4];
    const float* wo   = (const float*)d_in[5];
    const float* sink = (const float*)d_in[6];
    float* out = (float*)d_out;

    float *q_ptr, *k_ptr, *hs_ptr, *wq_ptr, *wk_ptr, *wv_ptr, *wo_ptr;
    cudaGetSymbolAddress((void**)&q_ptr, g_q);
    cudaGetSymbolAddress((void**)&k_ptr, g_k);
    cudaGetSymbolAddress((void**)&hs_ptr, g_hs);
    cudaGetSymbolAddress((void**)&wq_ptr, g_wq);
    cudaGetSymbolAddress((void**)&wk_ptr, g_wk);
    cudaGetSymbolAddress((void**)&wv_ptr, g_wv);
    cudaGetSymbolAddress((void**)&wo_ptr, g_wo);

    cudaFuncSetAttribute(qkv_gemm_kernel, cudaFuncAttributeMaxDynamicSharedMemorySize, GEMM_SMEM);
    cudaFuncSetAttribute(o_gemm_kernel,  cudaFuncAttributeMaxDynamicSharedMemorySize, GEMM_SMEM);

    /* tf32 pre-rounding of GEMM inputs */
    round_tf32_kernel<<<(SEQ*HIDDEN/4 + 255)/256, 256>>>(hs, hs_ptr, SEQ*HIDDEN/4);
    round_tf32_kernel<<<(HIDDEN*QDIM/4 + 255)/256, 256>>>(wq, wq_ptr, HIDDEN*QDIM/4);
    round_tf32_kernel<<<(HIDDEN*KVDIM/4 + 255)/256, 256>>>(wk, wk_ptr, HIDDEN*KVDIM/4);
    round_tf32_kernel<<<(HIDDEN*KVDIM/4 + 255)/256, 256>>>(wv, wv_ptr, HIDDEN*KVDIM/4);
    round_tf32_kernel<<<(QDIM*HIDDEN/4 + 255)/256, 256>>>(wo, wo_ptr, QDIM*HIDDEN/4);

    /* fused QKV projection */
    qkv_gemm_kernel<<<dim3(24, SEQ / GBM), 256, GEMM_SMEM>>>();

    /* RoPE */
    {
        int tq = SEQ * NQH * (HD / 2);
        rope_kernel<<<(tq + 255) / 256, 256>>>(q_ptr, pos, NQH);
        int tk = SEQ * NKVH * (HD / 2);
        rope_kernel<<<(tk + 255) / 256, 256>>>(k_ptr, pos, NKVH);
    }

    /* attention (bf16x3 tensor cores) */
    {
        int smem_words = 2 * AQT * KPAD + 2 * AKT * KPAD + 2 * (AKT/2) * VPAD;
        int smem = smem_words * 4;
        cudaFuncSetAttribute(attn_mma_kernel, cudaFuncAttributeMaxDynamicSharedMemorySize, smem);
        attn_mma_kernel<<<dim3(SEQ / AQT, NQH), 256, smem>>>(sink);
    }

    /* output projection */
    o_gemm_kernel<<<dim3(HIDDEN / GBN, SEQ / GBM), 256, GEMM_SMEM>>>(out);
}